// round 16
// baseline (speedup 1.0000x reference)
#include <cuda_runtime.h>
#include <cuda_fp16.h>
#include <mma.h>

using namespace nvcuda;

#define N_NODES 64000
#define N_EDGES 1024000
#define F 64
#define N_GRAPHS 128
#define DEG_CAP 64     // Poisson(16) degrees; P(deg>64) ~ 1e-26 on this dataset
#define POOL_NB 250
#define AGG_WARPS 8000 // 1000 blocks x 8 warps; each warp handles 8 nodes

typedef unsigned long long u64;

// ---------------- persistent device scratch (zero-init; self-restoring) ----------------
__device__ int   g_deg[N_NODES];              // zeroed by k_pool after use
__device__ int   g_col[N_NODES * DEG_CAP];    // bucket CSR, stride 64

__device__ __align__(16) float  g_yl[N_NODES * F];   // h @ Wl.T  (fp32, gathered)
__device__ __align__(16) float  g_yr[N_NODES * F];   // h @ Wr.T  (fp32, streamed)
__device__ __align__(16) __half g_hh[N_NODES * F];   // layer output (fp16)

__device__ __align__(16) float g_y2l[N_NODES * 2];
__device__ __align__(16) float g_y2r[N_NODES * 2];
__device__ float g_gsum[N_GRAPHS * 2];  // zeroed by k_pool after use
__device__ int   g_gcnt[N_GRAPHS];      // zeroed by k_pool after use
__device__ int   g_done;                // reset by k_pool

// packed f32x2 add (sm_100a)
__device__ __forceinline__ u64 fadd2(u64 a, u64 c) {
    u64 r; asm("add.rn.f32x2 %0,%1,%2;" : "=l"(r) : "l"(a), "l"(c)); return r;
}

// per-block dtype probe: int32 node-id pairs read as int64 are >= 2^32 w.h.p.
__device__ __forceinline__ int probe64(const void* ei) {
    const long long* p = (const long long*)ei;
    int ok = 1;
    #pragma unroll
    for (int i = 0; i < 8; i++) {
        long long v = p[i];
        if (v < 0 || v >= (long long)N_NODES) ok = 0;
    }
    return ok;
}

__device__ __forceinline__ int idx_at(const void* p, int i, int is64) {
    if (is64) return (int)((const long long*)p)[i];
    return ((const int*)p)[i];
}

// ---------------- one-pass bucket-CSR build (4 edges / thread) ----------------
__global__ void k_fill2(const void* __restrict__ ei,
                        const void* __restrict__ batch,
                        int e_lo, int e_hi, int do_batch) {
    __shared__ int s64;
    if (threadIdx.x == 0) s64 = probe64(ei);
    __syncthreads();
    int is64 = s64;
    int tid = blockIdx.x * blockDim.x + threadIdx.x;
    int e4 = e_lo + tid * 4;
    if (e4 < e_hi) {
        int d0, d1, d2, d3, s0, s1, s2, s3;
        if (is64) {
            const longlong2* pd = (const longlong2*)((const long long*)ei + N_EDGES + e4);
            const longlong2* ps = (const longlong2*)((const long long*)ei + e4);
            longlong2 a = pd[0], c = pd[1];
            longlong2 e = ps[0], f = ps[1];
            d0 = (int)a.x; d1 = (int)a.y; d2 = (int)c.x; d3 = (int)c.y;
            s0 = (int)e.x; s1 = (int)e.y; s2 = (int)f.x; s3 = (int)f.y;
        } else {
            int4 a = *(const int4*)((const int*)ei + N_EDGES + e4);
            int4 e = *(const int4*)((const int*)ei + e4);
            d0 = a.x; d1 = a.y; d2 = a.z; d3 = a.w;
            s0 = e.x; s1 = e.y; s2 = e.z; s3 = e.w;
        }
        int p0 = atomicAdd(&g_deg[d0], 1); if (p0 < DEG_CAP) g_col[d0 * DEG_CAP + p0] = s0;
        int p1 = atomicAdd(&g_deg[d1], 1); if (p1 < DEG_CAP) g_col[d1 * DEG_CAP + p1] = s1;
        int p2 = atomicAdd(&g_deg[d2], 1); if (p2 < DEG_CAP) g_col[d2 * DEG_CAP + p2] = s2;
        int p3 = atomicAdd(&g_deg[d3], 1); if (p3 < DEG_CAP) g_col[d3 * DEG_CAP + p3] = s3;
    }
    if (do_batch) {
        int n4 = tid * 4;
        if (n4 < N_NODES) {
            int b0, b1, b2, b3;
            if (is64) {
                const longlong2* p = (const longlong2*)batch;
                longlong2 a = p[tid * 2], c = p[tid * 2 + 1];
                b0 = (int)a.x; b1 = (int)a.y; b2 = (int)c.x; b3 = (int)c.y;
            } else {
                int4 a = ((const int4*)batch)[tid];
                b0 = a.x; b1 = a.y; b2 = a.z; b3 = a.w;
            }
            if (b0 == b3) {
                atomicAdd(&g_gcnt[b0], 4);
            } else {
                atomicAdd(&g_gcnt[b0], 1);
                atomicAdd(&g_gcnt[b1], 1);
                atomicAdd(&g_gcnt[b2], 1);
                atomicAdd(&g_gcnt[b3], 1);
            }
        }
    }
}

// ---------------- tensor-core transform: [yl | yr] = h @ [Wl | Wr].T ----------------
// 128-node tile per block, 256 threads (8 warps). wmma 16x16x16 fp16->fp32.
// BOTH C halves store directly from fragments to global (fp32) — no smem round-trip.
#define LDA 72
#define LDB 72
#define SMEM_BYTES 36864   // sA 128*72*2 + sB 128*72*2

__global__ void __launch_bounds__(256) k_transform(
        const float* __restrict__ x_ext, int use_x,
        const float* __restrict__ Wl,
        const float* __restrict__ Wr) {
    __shared__ __align__(16) char smem_raw[SMEM_BYTES];
    __half* sA = (__half*)smem_raw;                     // [128][LDA]
    __half* sB = (__half*)(smem_raw + 128 * LDA * 2);   // [128][LDB]

    int t = threadIdx.x;
    int base = blockIdx.x * 128;

    // stage A: 128 nodes x 64 features -> fp16, ld = LDA
    if (use_x) {
        #pragma unroll
        for (int j = 0; j < 8; j++) {
            int f = t + 256 * j;
            int row = f >> 4, q = f & 15;
            float4 v = *(const float4*)(x_ext + (size_t)(base + row) * F + q * 4);
            __half2* dst = (__half2*)&sA[row * LDA + q * 4];
            dst[0] = __floats2half2_rn(v.x, v.y);
            dst[1] = __floats2half2_rn(v.z, v.w);
        }
    } else {
        #pragma unroll
        for (int j = 0; j < 4; j++) {
            int f = t + 256 * j;
            int row = f >> 3, q = f & 7;
            uint4 v = *(const uint4*)(g_hh + (size_t)(base + row) * F + q * 8);
            *(uint4*)&sA[row * LDA + q * 8] = v;
        }
    }
    // stage B: rows 0..63 = Wl, 64..127 = Wr; [n][k] fp32 -> fp16, ld = LDB
    #pragma unroll
    for (int j = 0; j < 8; j++) {
        int f = t + 256 * j;
        int row = f >> 4, q = f & 15;
        const float* W = (row < 64) ? (Wl + (size_t)row * F) : (Wr + (size_t)(row - 64) * F);
        float4 v = *(const float4*)(W + q * 4);
        __half2* dst = (__half2*)&sB[row * LDB + q * 4];
        dst[0] = __floats2half2_rn(v.x, v.y);
        dst[1] = __floats2half2_rn(v.z, v.w);
    }
    __syncthreads();

    // MMA: C[128][128] = A[128][64] * B^T ; warp w owns M-strip w*16 (8 warps)
    int w = t >> 5;
    wmma::fragment<wmma::matrix_a, 16, 16, 16, __half, wmma::row_major> afrag[4];
    #pragma unroll
    for (int k = 0; k < 4; k++)
        wmma::load_matrix_sync(afrag[k], sA + (w * 16) * LDA + k * 16, LDA);

    wmma::fragment<wmma::accumulator, 16, 16, 16, float> cfrag[8];
    #pragma unroll
    for (int n = 0; n < 8; n++) {
        wmma::fill_fragment(cfrag[n], 0.0f);
        #pragma unroll
        for (int k = 0; k < 4; k++) {
            wmma::fragment<wmma::matrix_b, 16, 16, 16, __half, wmma::col_major> bfrag;
            wmma::load_matrix_sync(bfrag, sB + (n * 16) * LDB + k * 16, LDB);
            wmma::mma_sync(cfrag[n], afrag[k], bfrag, cfrag[n]);
        }
    }
    // yl half (cols 0..63) and yr half (cols 64..127): direct global stores (fp32, ld=F)
    #pragma unroll
    for (int n = 0; n < 4; n++)
        wmma::store_matrix_sync(g_yl + (size_t)(base + w * 16) * F + n * 16,
                                cfrag[n], F, wmma::mem_row_major);
    #pragma unroll
    for (int n = 4; n < 8; n++)
        wmma::store_matrix_sync(g_yr + (size_t)(base + w * 16) * F + (n - 4) * 16,
                                cfrag[n], F, wmma::mem_row_major);
}

// ---------------- aggregate + epilogue (multi-node warps + packed f32x2 adds) ----------------
// Each warp processes 8 nodes (node += AGG_WARPS); lane owns feature pair (2l, 2l+1).
// h = relu((1/deg) * sum yl[src] + yr + b) -> g_hh (fp16)
// fuse_out: y2l = h@Wlo.T, y2r = h@Wro.T via warp reduction; skip g_hh store.
__global__ void __launch_bounds__(256) k_aggr(
        const float* __restrict__ b,
        const float* __restrict__ Wlo,
        const float* __restrict__ Wro,
        int fuse_out) {
    __shared__ float sw[4 * F];   // Wlo row0, Wlo row1, Wro row0, Wro row1
    if (fuse_out) {
        int t = threadIdx.x;
        if (t < 128) sw[t] = Wlo[t];
        else if (t < 256) sw[t] = Wro[t - 128];
        __syncthreads();
    }
    int gwarp = (blockIdx.x * blockDim.x + threadIdx.x) >> 5;  // 0..AGG_WARPS-1
    int lane = threadIdx.x & 31;
    const u64* yl = (const u64*)g_yl;   // 32 packed f32x2 per node row
    float b0 = b[lane * 2], b1 = b[lane * 2 + 1];

    for (int node = gwarp; node < N_NODES; node += AGG_WARPS) {
        int deg = min(g_deg[node], DEG_CAP);
        const int* col = g_col + node * DEG_CAP;   // 256B-aligned rows
        u64 acc0 = 0ull, acc1 = 0ull;              // packed (+0.0f, +0.0f)
        int j = 0;
        for (; j + 8 <= deg; j += 8) {
            int4 c0 = *(const int4*)(col + j);
            int4 c1 = *(const int4*)(col + j + 4);
            u64 v0 = yl[c0.x * 32 + lane];
            u64 v1 = yl[c0.y * 32 + lane];
            u64 v2 = yl[c0.z * 32 + lane];
            u64 v3 = yl[c0.w * 32 + lane];
            u64 v4 = yl[c1.x * 32 + lane];
            u64 v5 = yl[c1.y * 32 + lane];
            u64 v6 = yl[c1.z * 32 + lane];
            u64 v7 = yl[c1.w * 32 + lane];
            acc0 = fadd2(acc0, v0); acc1 = fadd2(acc1, v1);
            acc0 = fadd2(acc0, v2); acc1 = fadd2(acc1, v3);
            acc0 = fadd2(acc0, v4); acc1 = fadd2(acc1, v5);
            acc0 = fadd2(acc0, v6); acc1 = fadd2(acc1, v7);
        }
        for (; j + 2 <= deg; j += 2) {
            u64 v0 = yl[col[j] * 32 + lane];
            u64 v1 = yl[col[j + 1] * 32 + lane];
            acc0 = fadd2(acc0, v0); acc1 = fadd2(acc1, v1);
        }
        if (j < deg)
            acc0 = fadd2(acc0, yl[col[j] * 32 + lane]);
        u64 accs = fadd2(acc0, acc1);
        float ax, ay;
        asm("mov.b64 {%0,%1},%2;" : "=f"(ax), "=f"(ay) : "l"(accs));

        float id = (deg > 0) ? __frcp_rn((float)deg) : 0.0f;
        float2 r = *(const float2*)(g_yr + (size_t)node * F + lane * 2);
        float o0 = fmaxf(ax * id + r.x + b0, 0.0f);
        float o1 = fmaxf(ay * id + r.y + b1, 0.0f);
        if (!fuse_out) {
            *(__half2*)(g_hh + (size_t)node * F + lane * 2) = __floats2half2_rn(o0, o1);
        } else {
            float p0 = o0 * sw[0 * F + lane * 2] + o1 * sw[0 * F + lane * 2 + 1];
            float p1 = o0 * sw[1 * F + lane * 2] + o1 * sw[1 * F + lane * 2 + 1];
            float p2 = o0 * sw[2 * F + lane * 2] + o1 * sw[2 * F + lane * 2 + 1];
            float p3 = o0 * sw[3 * F + lane * 2] + o1 * sw[3 * F + lane * 2 + 1];
            #pragma unroll
            for (int o = 16; o > 0; o >>= 1) {
                p0 += __shfl_xor_sync(0xffffffffu, p0, o);
                p1 += __shfl_xor_sync(0xffffffffu, p1, o);
                p2 += __shfl_xor_sync(0xffffffffu, p2, o);
                p3 += __shfl_xor_sync(0xffffffffu, p3, o);
            }
            if (lane == 0) {
                *(float2*)(g_y2l + (size_t)node * 2) = make_float2(p0, p1);
                *(float2*)(g_y2r + (size_t)node * 2) = make_float2(p2, p3);
            }
        }
    }
}

// ---------------- output aggregation + pool + final (merged, last-block-done) ----------------
// also restores g_deg = 0 for the next replay.
__global__ void k_pool(const void* __restrict__ ei,
                       const void* __restrict__ batch,
                       const float* __restrict__ b_out,
                       float* __restrict__ out) {
    __shared__ int s64;
    __shared__ int s_last;
    if (threadIdx.x == 0) s64 = probe64(ei);
    __syncthreads();
    int is64 = s64;
    int i = blockIdx.x * blockDim.x + threadIdx.x;   // 250*256 == N_NODES exactly
    int deg = min(g_deg[i], DEG_CAP);
    const int* col = g_col + i * DEG_CAP;
    float a0 = 0.0f, a1 = 0.0f;
    for (int j = 0; j < deg; j++) {
        int src = col[j];
        float2 v = *(const float2*)(g_y2l + (size_t)src * 2);
        a0 += v.x;
        a1 += v.y;
    }
    float id = (deg > 0) ? __frcp_rn((float)deg) : 0.0f;
    float o0 = a0 * id + g_y2r[i * 2 + 0] + b_out[0];
    float o1 = a1 * id + g_y2r[i * 2 + 1] + b_out[1];
    int g = idx_at(batch, i, is64);
    atomicAdd(&g_gsum[g * 2 + 0], o0);
    atomicAdd(&g_gsum[g * 2 + 1], o1);
    g_deg[i] = 0;                        // restore for next replay
    __threadfence();
    if (threadIdx.x == 0)
        s_last = (atomicAdd(&g_done, 1) == gridDim.x - 1);
    __syncthreads();
    if (s_last) {
        int t = threadIdx.x;
        volatile float* vs = g_gsum;
        if (t < N_GRAPHS * 2) {
            int gg = t >> 1;
            float c = (float)max(g_gcnt[gg], 1);
            out[t] = vs[t] / c;
            g_gsum[t] = 0.0f;            // restore
        }
        if (t < N_GRAPHS) g_gcnt[t] = 0; // restore
        if (t == 0) g_done = 0;          // restore
    }
}

// ---------------- launch ----------------
extern "C" void kernel_launch(void* const* d_in, const int* in_sizes, int n_in,
                              void* d_out, int out_size) {
    const float* x      = (const float*)d_in[0];
    const void*  ei     = d_in[1];   // int64 or int32 [2, E]
    const void*  batch  = d_in[2];   // int64 or int32 [N]
    const float* Wl     = (const float*)d_in[3];   // [3,64,64]
    const float* Wr     = (const float*)d_in[4];   // [3,64,64]
    const float* b      = (const float*)d_in[5];   // [3,64]
    const float* Wl_out = (const float*)d_in[6];   // [2,64]
    const float* Wr_out = (const float*)d_in[7];   // [2,64]
    const float* b_out  = (const float*)d_in[8];   // [2]
    float*       out    = (float*)d_out;

    // lazy one-time host resources (created on the uncaptured correctness run)
    static cudaStream_t s2 = 0;
    static cudaEvent_t ev0 = 0, ev1 = 0;
    if (s2 == 0) {
        cudaStreamCreateWithFlags(&s2, cudaStreamNonBlocking);
        cudaEventCreateWithFlags(&ev0, cudaEventDisableTiming);
        cudaEventCreateWithFlags(&ev1, cudaEventDisableTiming);
    }

    const int TGRID = N_NODES / 128;                // 500 blocks, 128 nodes each
    const int AGRID = AGG_WARPS / 8;                // 1000 blocks, 8 warps each
    const int E_HALF = N_EDGES / 2;
    const int FGRID = (E_HALF / 4 + 255) / 256;

    // fork point recorded before any work: transform0 depends only on inputs
    cudaEventRecord(ev0, 0);
    cudaStreamWaitEvent(s2, ev0, 0);

    // one-pass bucket CSR (two halves) on main; transform0 overlaps on s2
    k_fill2<<<FGRID, 256>>>(ei, batch, 0, E_HALF, 1);        // #0
    k_fill2<<<FGRID, 256>>>(ei, batch, E_HALF, N_EDGES, 0);  // #1
    k_transform<<<TGRID, 256, 0, s2>>>(x, 1, Wl + 0 * F * F, Wr + 0 * F * F); // #2
    cudaEventRecord(ev1, s2);

    // join: aggregation layer 0 needs both CSR and transform0
    cudaStreamWaitEvent(0, ev1, 0);

    k_aggr<<<AGRID, 256>>>(b + 0 * F, Wl_out, Wr_out, 0);    // #3 (profiled)
    k_transform<<<TGRID, 256>>>(x, 0, Wl + 1 * F * F, Wr + 1 * F * F);
    k_aggr<<<AGRID, 256>>>(b + 1 * F, Wl_out, Wr_out, 0);
    k_transform<<<TGRID, 256>>>(x, 0, Wl + 2 * F * F, Wr + 2 * F * F);
    // layer 2: output-layer transform fused into the epilogue
    k_aggr<<<AGRID, 256>>>(b + 2 * F, Wl_out, Wr_out, 1);

    // output aggregation + global mean pool + final (merged)
    k_pool<<<POOL_NB, 256>>>(ei, batch, b_out, out);
}

// round 17
// speedup vs baseline: 1.1981x; 1.1981x over previous
#include <cuda_runtime.h>
#include <cuda_fp16.h>
#include <mma.h>

using namespace nvcuda;

#define N_NODES 64000
#define N_EDGES 1024000
#define F 64
#define N_GRAPHS 128
#define DEG_CAP 64     // Poisson(16) degrees; P(deg>64) ~ 1e-26 on this dataset
#define POOL_NB 250

typedef unsigned long long u64;

// ---------------- persistent device scratch (zero-init; self-restoring) ----------------
__device__ int   g_deg[N_NODES];              // zeroed by k_pool after use
__device__ int   g_col[N_NODES * DEG_CAP];    // bucket CSR, stride 64

__device__ __align__(16) __half g_ylh[N_NODES * F];  // h @ Wl.T  (fp16, gathered)
__device__ __align__(16) float  g_yr[N_NODES * F];   // h @ Wr.T  (fp32, streamed)
__device__ __align__(16) __half g_hh[N_NODES * F];   // layer output (fp16)

__device__ __align__(16) float g_y2l[N_NODES * 2];
__device__ __align__(16) float g_y2r[N_NODES * 2];
__device__ float g_gsum[N_GRAPHS * 2];  // zeroed by k_pool after use
__device__ int   g_gcnt[N_GRAPHS];      // zeroed by k_pool after use
__device__ int   g_done;                // reset by k_pool

// per-block dtype probe: int32 node-id pairs read as int64 are >= 2^32 w.h.p.
__device__ __forceinline__ int probe64(const void* ei) {
    const long long* p = (const long long*)ei;
    int ok = 1;
    #pragma unroll
    for (int i = 0; i < 8; i++) {
        long long v = p[i];
        if (v < 0 || v >= (long long)N_NODES) ok = 0;
    }
    return ok;
}

__device__ __forceinline__ int idx_at(const void* p, int i, int is64) {
    if (is64) return (int)((const long long*)p)[i];
    return ((const int*)p)[i];
}

// ---------------- one-pass bucket-CSR build (4 edges / thread) + graph sizes ----------------
__global__ void k_fill(const void* __restrict__ ei,
                       const void* __restrict__ batch) {
    __shared__ int s64;
    if (threadIdx.x == 0) s64 = probe64(ei);
    __syncthreads();
    int is64 = s64;
    int tid = blockIdx.x * blockDim.x + threadIdx.x;
    int e4 = tid * 4;
    if (e4 < N_EDGES) {
        int d0, d1, d2, d3, s0, s1, s2, s3;
        if (is64) {
            const longlong2* pd = (const longlong2*)((const long long*)ei + N_EDGES + e4);
            const longlong2* ps = (const longlong2*)((const long long*)ei + e4);
            longlong2 a = pd[0], c = pd[1];
            longlong2 e = ps[0], f = ps[1];
            d0 = (int)a.x; d1 = (int)a.y; d2 = (int)c.x; d3 = (int)c.y;
            s0 = (int)e.x; s1 = (int)e.y; s2 = (int)f.x; s3 = (int)f.y;
        } else {
            int4 a = *(const int4*)((const int*)ei + N_EDGES + e4);
            int4 e = *(const int4*)((const int*)ei + e4);
            d0 = a.x; d1 = a.y; d2 = a.z; d3 = a.w;
            s0 = e.x; s1 = e.y; s2 = e.z; s3 = e.w;
        }
        int p0 = atomicAdd(&g_deg[d0], 1); if (p0 < DEG_CAP) g_col[d0 * DEG_CAP + p0] = s0;
        int p1 = atomicAdd(&g_deg[d1], 1); if (p1 < DEG_CAP) g_col[d1 * DEG_CAP + p1] = s1;
        int p2 = atomicAdd(&g_deg[d2], 1); if (p2 < DEG_CAP) g_col[d2 * DEG_CAP + p2] = s2;
        int p3 = atomicAdd(&g_deg[d3], 1); if (p3 < DEG_CAP) g_col[d3 * DEG_CAP + p3] = s3;
    }
    if (e4 < N_NODES) {
        int b0, b1, b2, b3;
        if (is64) {
            const longlong2* p = (const longlong2*)batch;
            longlong2 a = p[tid * 2], c = p[tid * 2 + 1];
            b0 = (int)a.x; b1 = (int)a.y; b2 = (int)c.x; b3 = (int)c.y;
        } else {
            int4 a = ((const int4*)batch)[tid];
            b0 = a.x; b1 = a.y; b2 = a.z; b3 = a.w;
        }
        if (b0 == b3) {
            atomicAdd(&g_gcnt[b0], 4);
        } else {
            atomicAdd(&g_gcnt[b0], 1);
            atomicAdd(&g_gcnt[b1], 1);
            atomicAdd(&g_gcnt[b2], 1);
            atomicAdd(&g_gcnt[b3], 1);
        }
    }
}

// ---------------- tensor-core transform: [ylh | yr] = h @ [Wl | Wr].T ----------------
// 128-node tile per block, 256 threads (8 warps). wmma 16x16x16 fp16->fp32.
// yr fragments store DIRECTLY to global; ylh (fp16 convert) round-trips smem.
#define LDA 72
#define LDB 72
#define LDC 68
#define SMEM_BYTES 36864   // sA 128*72*2 + sB 128*72*2; sC 128*68*4=34816 aliases

__global__ void __launch_bounds__(256) k_transform(
        const float* __restrict__ x_ext, int use_x,
        const float* __restrict__ Wl,
        const float* __restrict__ Wr) {
    __shared__ __align__(16) char smem_raw[SMEM_BYTES];
    __half* sA = (__half*)smem_raw;                     // [128][LDA]
    __half* sB = (__half*)(smem_raw + 128 * LDA * 2);   // [128][LDB]
    float*  sC = (float*)smem_raw;                      // [128][LDC] (aliased)

    int t = threadIdx.x;
    int base = blockIdx.x * 128;

    // stage A: 128 nodes x 64 features -> fp16, ld = LDA
    if (use_x) {
        #pragma unroll
        for (int j = 0; j < 8; j++) {
            int f = t + 256 * j;
            int row = f >> 4, q = f & 15;
            float4 v = *(const float4*)(x_ext + (size_t)(base + row) * F + q * 4);
            __half2* dst = (__half2*)&sA[row * LDA + q * 4];
            dst[0] = __floats2half2_rn(v.x, v.y);
            dst[1] = __floats2half2_rn(v.z, v.w);
        }
    } else {
        #pragma unroll
        for (int j = 0; j < 4; j++) {
            int f = t + 256 * j;
            int row = f >> 3, q = f & 7;
            uint4 v = *(const uint4*)(g_hh + (size_t)(base + row) * F + q * 8);
            *(uint4*)&sA[row * LDA + q * 8] = v;
        }
    }
    // stage B: rows 0..63 = Wl, 64..127 = Wr; [n][k] fp32 -> fp16, ld = LDB
    #pragma unroll
    for (int j = 0; j < 8; j++) {
        int f = t + 256 * j;
        int row = f >> 4, q = f & 15;
        const float* W = (row < 64) ? (Wl + (size_t)row * F) : (Wr + (size_t)(row - 64) * F);
        float4 v = *(const float4*)(W + q * 4);
        __half2* dst = (__half2*)&sB[row * LDB + q * 4];
        dst[0] = __floats2half2_rn(v.x, v.y);
        dst[1] = __floats2half2_rn(v.z, v.w);
    }
    __syncthreads();

    // MMA: C[128][128] = A[128][64] * B^T ; warp w owns M-strip w*16 (8 warps)
    int w = t >> 5;
    wmma::fragment<wmma::matrix_a, 16, 16, 16, __half, wmma::row_major> afrag[4];
    #pragma unroll
    for (int k = 0; k < 4; k++)
        wmma::load_matrix_sync(afrag[k], sA + (w * 16) * LDA + k * 16, LDA);

    wmma::fragment<wmma::accumulator, 16, 16, 16, float> cfrag[8];
    #pragma unroll
    for (int n = 0; n < 8; n++) {
        wmma::fill_fragment(cfrag[n], 0.0f);
        #pragma unroll
        for (int k = 0; k < 4; k++) {
            wmma::fragment<wmma::matrix_b, 16, 16, 16, __half, wmma::col_major> bfrag;
            wmma::load_matrix_sync(bfrag, sB + (n * 16) * LDB + k * 16, LDB);
            wmma::mma_sync(cfrag[n], afrag[k], bfrag, cfrag[n]);
        }
    }
    // yr half (cols 64..127): store fragments DIRECTLY to global (fp32, ld=F)
    #pragma unroll
    for (int n = 4; n < 8; n++)
        wmma::store_matrix_sync(g_yr + (size_t)(base + w * 16) * F + (n - 4) * 16,
                                cfrag[n], F, wmma::mem_row_major);
    __syncthreads();   // all A/B smem reads complete before sC aliases the region
    #pragma unroll
    for (int n = 0; n < 4; n++)
        wmma::store_matrix_sync(sC + (w * 16) * LDC + n * 16, cfrag[n], LDC, wmma::mem_row_major);
    __syncthreads();

    // writeout ylh: 128 rows x 16 float4-chunks = 2048, 8 iters; fp32 -> fp16
    #pragma unroll
    for (int j = 0; j < 8; j++) {
        int f = t + 256 * j;
        int row = f >> 4, q = f & 15;
        float4 v = *(const float4*)&sC[row * LDC + q * 4];
        __half2* dst = (__half2*)(g_ylh + (size_t)(base + row) * F + q * 4);
        dst[0] = __floats2half2_rn(v.x, v.y);
        dst[1] = __floats2half2_rn(v.z, v.w);
    }
}

// ---------------- aggregate + epilogue (R13 layout: warp/node, fp32 accumulation) ----------------
// h = relu((1/deg) * sum ylh[src] + yr + b) -> g_hh (fp16); lane owns features (2l, 2l+1)
// int4 neighbor-index loads (256B-aligned rows). fp32 accumulation -> deterministic.
// fuse_out: y2l = h@Wlo.T, y2r = h@Wro.T via warp reduction; skip g_hh store.
__global__ void k_aggr(const float* __restrict__ b,
                       const float* __restrict__ Wlo,
                       const float* __restrict__ Wro,
                       int fuse_out) {
    __shared__ float sw[4 * F];   // Wlo row0, Wlo row1, Wro row0, Wro row1
    if (fuse_out) {
        int t = threadIdx.x;
        if (t < 128) sw[t] = Wlo[t];
        else if (t < 256) sw[t] = Wro[t - 128];
        __syncthreads();
    }
    int warp = (blockIdx.x * blockDim.x + threadIdx.x) >> 5;
    int lane = threadIdx.x & 31;
    if (warp >= N_NODES) return;
    const __half2* yl = (const __half2*)g_ylh;   // 32 half2 per node row
    int deg = min(g_deg[warp], DEG_CAP);
    const int* col = g_col + warp * DEG_CAP;
    float ax = 0.0f, ay = 0.0f;
    int j = 0;
    for (; j + 8 <= deg; j += 8) {
        int4 c0 = *(const int4*)(col + j);
        int4 c1 = *(const int4*)(col + j + 4);
        float2 f0 = __half22float2(yl[c0.x * 32 + lane]);
        float2 f1 = __half22float2(yl[c0.y * 32 + lane]);
        float2 f2 = __half22float2(yl[c0.z * 32 + lane]);
        float2 f3 = __half22float2(yl[c0.w * 32 + lane]);
        float2 f4 = __half22float2(yl[c1.x * 32 + lane]);
        float2 f5 = __half22float2(yl[c1.y * 32 + lane]);
        float2 f6 = __half22float2(yl[c1.z * 32 + lane]);
        float2 f7 = __half22float2(yl[c1.w * 32 + lane]);
        ax += ((f0.x + f1.x) + (f2.x + f3.x)) + ((f4.x + f5.x) + (f6.x + f7.x));
        ay += ((f0.y + f1.y) + (f2.y + f3.y)) + ((f4.y + f5.y) + (f6.y + f7.y));
    }
    for (; j + 2 <= deg; j += 2) {
        int i0 = col[j], i1 = col[j + 1];
        float2 f0 = __half22float2(yl[i0 * 32 + lane]);
        float2 f1 = __half22float2(yl[i1 * 32 + lane]);
        ax += f0.x + f1.x;
        ay += f0.y + f1.y;
    }
    if (j < deg) {
        float2 f0 = __half22float2(yl[col[j] * 32 + lane]);
        ax += f0.x;
        ay += f0.y;
    }
    float id = (deg > 0) ? __frcp_rn((float)deg) : 0.0f;
    float2 r = *(const float2*)(g_yr + (size_t)warp * F + lane * 2);
    float b0 = b[lane * 2], b1 = b[lane * 2 + 1];
    float o0 = fmaxf(ax * id + r.x + b0, 0.0f);
    float o1 = fmaxf(ay * id + r.y + b1, 0.0f);
    if (!fuse_out) {
        *(__half2*)(g_hh + (size_t)warp * F + lane * 2) = __floats2half2_rn(o0, o1);
    } else {
        float p0 = o0 * sw[0 * F + lane * 2] + o1 * sw[0 * F + lane * 2 + 1];
        float p1 = o0 * sw[1 * F + lane * 2] + o1 * sw[1 * F + lane * 2 + 1];
        float p2 = o0 * sw[2 * F + lane * 2] + o1 * sw[2 * F + lane * 2 + 1];
        float p3 = o0 * sw[3 * F + lane * 2] + o1 * sw[3 * F + lane * 2 + 1];
        #pragma unroll
        for (int o = 16; o > 0; o >>= 1) {
            p0 += __shfl_xor_sync(0xffffffffu, p0, o);
            p1 += __shfl_xor_sync(0xffffffffu, p1, o);
            p2 += __shfl_xor_sync(0xffffffffu, p2, o);
            p3 += __shfl_xor_sync(0xffffffffu, p3, o);
        }
        if (lane == 0) {
            *(float2*)(g_y2l + (size_t)warp * 2) = make_float2(p0, p1);
            *(float2*)(g_y2r + (size_t)warp * 2) = make_float2(p2, p3);
        }
    }
}

// ---------------- output aggregation + pool + final (merged, last-block-done) ----------------
// also restores g_deg = 0 for the next replay.
__global__ void k_pool(const void* __restrict__ ei,
                       const void* __restrict__ batch,
                       const float* __restrict__ b_out,
                       float* __restrict__ out) {
    __shared__ int s64;
    __shared__ int s_last;
    if (threadIdx.x == 0) s64 = probe64(ei);
    __syncthreads();
    int is64 = s64;
    int i = blockIdx.x * blockDim.x + threadIdx.x;   // 250*256 == N_NODES exactly
    int deg = min(g_deg[i], DEG_CAP);
    const int* col = g_col + i * DEG_CAP;
    float a0 = 0.0f, a1 = 0.0f;
    for (int j = 0; j < deg; j++) {
        int src = col[j];
        float2 v = *(const float2*)(g_y2l + (size_t)src * 2);
        a0 += v.x;
        a1 += v.y;
    }
    float id = (deg > 0) ? __frcp_rn((float)deg) : 0.0f;
    float o0 = a0 * id + g_y2r[i * 2 + 0] + b_out[0];
    float o1 = a1 * id + g_y2r[i * 2 + 1] + b_out[1];
    int g = idx_at(batch, i, is64);
    atomicAdd(&g_gsum[g * 2 + 0], o0);
    atomicAdd(&g_gsum[g * 2 + 1], o1);
    g_deg[i] = 0;                        // restore for next replay
    __threadfence();
    if (threadIdx.x == 0)
        s_last = (atomicAdd(&g_done, 1) == gridDim.x - 1);
    __syncthreads();
    if (s_last) {
        int t = threadIdx.x;
        volatile float* vs = g_gsum;
        if (t < N_GRAPHS * 2) {
            int gg = t >> 1;
            float c = (float)max(g_gcnt[gg], 1);
            out[t] = vs[t] / c;
            g_gsum[t] = 0.0f;            // restore
        }
        if (t < N_GRAPHS) g_gcnt[t] = 0; // restore
        if (t == 0) g_done = 0;          // restore
    }
}

// ---------------- launch ----------------
extern "C" void kernel_launch(void* const* d_in, const int* in_sizes, int n_in,
                              void* d_out, int out_size) {
    const float* x      = (const float*)d_in[0];
    const void*  ei     = d_in[1];   // int64 or int32 [2, E]
    const void*  batch  = d_in[2];   // int64 or int32 [N]
    const float* Wl     = (const float*)d_in[3];   // [3,64,64]
    const float* Wr     = (const float*)d_in[4];   // [3,64,64]
    const float* b      = (const float*)d_in[5];   // [3,64]
    const float* Wl_out = (const float*)d_in[6];   // [2,64]
    const float* Wr_out = (const float*)d_in[7];   // [2,64]
    const float* b_out  = (const float*)d_in[8];   // [2]
    float*       out    = (float*)d_out;

    // lazy one-time host resources (created on the uncaptured correctness run)
    static cudaStream_t s2 = 0;
    static cudaEvent_t ev0 = 0, ev1 = 0;
    if (s2 == 0) {
        cudaStreamCreateWithFlags(&s2, cudaStreamNonBlocking);
        cudaEventCreateWithFlags(&ev0, cudaEventDisableTiming);
        cudaEventCreateWithFlags(&ev1, cudaEventDisableTiming);
    }

    const int TGRID = N_NODES / 128;                // 500 blocks, 128 nodes each
    const int AGRID = (N_NODES * 32 + 255) / 256;   // 8000 blocks, warp per node
    const int FGRID = (N_EDGES / 4 + 255) / 256;    // 1000 blocks, 4 edges/thread

    // fork point recorded before any work: transform0 depends only on inputs
    cudaEventRecord(ev0, 0);
    cudaStreamWaitEvent(s2, ev0, 0);

    // one-pass bucket CSR on main; transform0 overlaps on s2
    k_fill<<<FGRID, 256>>>(ei, batch);                        // #0
    k_transform<<<TGRID, 256, 0, s2>>>(x, 1, Wl + 0 * F * F, Wr + 0 * F * F); // #1
    cudaEventRecord(ev1, s2);

    // join: aggregation layer 0 needs both CSR and transform0
    cudaStreamWaitEvent(0, ev1, 0);

    k_aggr<<<AGRID, 256>>>(b + 0 * F, Wl_out, Wr_out, 0);     // #2
    k_transform<<<TGRID, 256>>>(x, 0, Wl + 1 * F * F, Wr + 1 * F * F);  // #3 (profiled)
    k_aggr<<<AGRID, 256>>>(b + 1 * F, Wl_out, Wr_out, 0);
    k_transform<<<TGRID, 256>>>(x, 0, Wl + 2 * F * F, Wr + 2 * F * F);
    // layer 2: output-layer transform fused into the epilogue
    k_aggr<<<AGRID, 256>>>(b + 2 * F, Wl_out, Wr_out, 1);

    // output aggregation + global mean pool + final (merged)
    k_pool<<<POOL_NB, 256>>>(ei, batch, b_out, out);
}